// round 1
// baseline (speedup 1.0000x reference)
#include <cuda_runtime.h>
#include <math.h>

// Problem constants
#define D_    1024
#define H_    16
#define DH_   64
#define HID_  4096
#define B_    4
#define S_    1024
#define M_    4096   // B_*S_

// ---------------------------------------------------------------------------
// Scratch (static __device__ arrays; no allocations allowed)
// ---------------------------------------------------------------------------
__device__ float g_Wq[D_ * D_];
__device__ float g_Wk[D_ * D_];
__device__ float g_Wv[D_ * D_];
__device__ float g_Q[M_ * D_];
__device__ float g_K[M_ * D_];
__device__ float g_V[M_ * D_];
__device__ float g_attn[M_ * D_];
__device__ float g_x1[M_ * D_];
__device__ float g_x2[M_ * D_];
__device__ float g_tmp[M_ * D_];
__device__ float g_ffh[M_ * HID_];

// ---------------------------------------------------------------------------
// Repack per-head weight [H, D, DH] -> [D, H*DH] row-major
// ---------------------------------------------------------------------------
__global__ void repack_w_kernel(const float* __restrict__ W, float* __restrict__ Wc)
{
    int idx = blockIdx.x * blockDim.x + threadIdx.x;   // over D_*D_
    int d = idx >> 10;          // / 1024
    int f = idx & 1023;
    int h = f >> 6;
    int e = f & 63;
    Wc[idx] = W[h * (D_ * DH_) + d * DH_ + e];
}

// ---------------------------------------------------------------------------
// Generic SGEMM: C = A[MxK] * B[KxN] + bias (+ residual) (or ReLU)
// MODE 0: +bias   MODE 1: +bias+residual   MODE 2: relu(+bias)
// BM=BN=128, BK=16, 256 threads, 8x8 thread tile
// ---------------------------------------------------------------------------
template <int MODE>
__global__ void __launch_bounds__(256, 2) gemm_kernel(
    const float* __restrict__ A, const float* __restrict__ Bm,
    const float* __restrict__ bias, const float* __restrict__ res,
    float* __restrict__ C, int M, int N, int K)
{
    __shared__ float As[16 * 128];
    __shared__ float Bs[16 * 128];

    const int tid = threadIdx.x;
    const int tx = tid & 15;
    const int ty = tid >> 4;
    const int rowBase = blockIdx.y * 128;
    const int colBase = blockIdx.x * 128;

    const int ar = tid >> 1;            // 0..127
    const int ac = (tid & 1) * 8;       // 0 or 8
    const int br = tid >> 5;            // 0..7
    const int bc = (tid & 31) * 4;      // 0..124

    const float* Aptr = A + (size_t)(rowBase + ar) * K + ac;
    const float* Bptr = Bm + (size_t)br * N + colBase + bc;

    float acc[8][8];
#pragma unroll
    for (int i = 0; i < 8; i++)
#pragma unroll
        for (int j = 0; j < 8; j++) acc[i][j] = 0.f;

    for (int k0 = 0; k0 < K; k0 += 16) {
        float4 a0 = *(const float4*)(Aptr + k0);
        float4 a1 = *(const float4*)(Aptr + k0 + 4);
        float4 b0 = *(const float4*)(Bptr + (size_t)k0 * N);
        float4 b1 = *(const float4*)(Bptr + (size_t)(k0 + 8) * N);

        As[(ac + 0) * 128 + ar] = a0.x;
        As[(ac + 1) * 128 + ar] = a0.y;
        As[(ac + 2) * 128 + ar] = a0.z;
        As[(ac + 3) * 128 + ar] = a0.w;
        As[(ac + 4) * 128 + ar] = a1.x;
        As[(ac + 5) * 128 + ar] = a1.y;
        As[(ac + 6) * 128 + ar] = a1.z;
        As[(ac + 7) * 128 + ar] = a1.w;
        *(float4*)&Bs[br * 128 + bc] = b0;
        *(float4*)&Bs[(br + 8) * 128 + bc] = b1;
        __syncthreads();

#pragma unroll
        for (int kk = 0; kk < 16; kk++) {
            float ra[8], rb[8];
            *(float4*)&ra[0] = *(const float4*)&As[kk * 128 + ty * 8];
            *(float4*)&ra[4] = *(const float4*)&As[kk * 128 + ty * 8 + 4];
            *(float4*)&rb[0] = *(const float4*)&Bs[kk * 128 + tx * 8];
            *(float4*)&rb[4] = *(const float4*)&Bs[kk * 128 + tx * 8 + 4];
#pragma unroll
            for (int i = 0; i < 8; i++)
#pragma unroll
                for (int j = 0; j < 8; j++) acc[i][j] += ra[i] * rb[j];
        }
        __syncthreads();
    }

#pragma unroll
    for (int i = 0; i < 8; i++) {
        int r = rowBase + ty * 8 + i;
#pragma unroll
        for (int jj = 0; jj < 2; jj++) {
            int c = colBase + tx * 8 + jj * 4;
            float4 bv = *(const float4*)(bias + c);
            float4 o;
            o.x = acc[i][jj * 4 + 0] + bv.x;
            o.y = acc[i][jj * 4 + 1] + bv.y;
            o.z = acc[i][jj * 4 + 2] + bv.z;
            o.w = acc[i][jj * 4 + 3] + bv.w;
            if (MODE == 1) {
                float4 rv = *(const float4*)(res + (size_t)r * N + c);
                o.x += rv.x; o.y += rv.y; o.z += rv.z; o.w += rv.w;
            }
            if (MODE == 2) {
                o.x = fmaxf(o.x, 0.f); o.y = fmaxf(o.y, 0.f);
                o.z = fmaxf(o.z, 0.f); o.w = fmaxf(o.w, 0.f);
            }
            *(float4*)(C + (size_t)r * N + c) = o;
        }
    }
}

// ---------------------------------------------------------------------------
// Fused attention (flash-style, online softmax)
// Q,K,V in [B*S, H*DH] row-major (per-head slice at col h*DH)
// Grid: (S/128 q-tiles, H, B); 256 threads; out in [B*S, H*DH]
// ---------------------------------------------------------------------------
#define AQ   128
#define AKV  64
#define ASTR 65

__global__ void __launch_bounds__(256) attn_kernel(
    const float* __restrict__ Qg, const float* __restrict__ Kg,
    const float* __restrict__ Vg, float* __restrict__ Og)
{
    extern __shared__ float sm[];
    float* sQ = sm;                       // AQ  x ASTR
    float* sP = sQ + AQ * ASTR;           // AQ  x ASTR
    float* sK = sP + AQ * ASTR;           // AKV x ASTR
    float* sV = sK + AKV * ASTR;          // AKV x ASTR

    const int b = blockIdx.z, h = blockIdx.y;
    const int q0 = blockIdx.x * AQ;
    const int tid = threadIdx.x;
    const int tx = tid & 15;
    const int ty = tid >> 4;

    const float* Qb = Qg + (size_t)(b * S_ + q0) * D_ + h * DH_;
    const float* Kb = Kg + (size_t)(b * S_) * D_ + h * DH_;
    const float* Vb = Vg + (size_t)(b * S_) * D_ + h * DH_;

    // load Q tile (pre-scaled by 1/sqrt(DH) = 0.125)
#pragma unroll
    for (int u = 0; u < 8; u++) {
        int v = u * 256 + tid;            // 0..2047 float4 slots
        int r = v >> 4;
        int c4 = v & 15;
        float4 q = *(const float4*)(Qb + (size_t)r * D_ + c4 * 4);
        float* dst = sQ + r * ASTR + c4 * 4;
        dst[0] = q.x * 0.125f; dst[1] = q.y * 0.125f;
        dst[2] = q.z * 0.125f; dst[3] = q.w * 0.125f;
    }

    float m[8], l[8], acc[8][4];
#pragma unroll
    for (int i = 0; i < 8; i++) {
        m[i] = -1e30f; l[i] = 0.f;
#pragma unroll
        for (int j = 0; j < 4; j++) acc[i][j] = 0.f;
    }

    for (int kt = 0; kt < S_ / AKV; kt++) {
        __syncthreads();   // previous PV done (and Q visible on first iter)
#pragma unroll
        for (int u = 0; u < 4; u++) {
            int v = u * 256 + tid;        // 0..1023
            int r = v >> 4;
            int c4 = v & 15;
            float4 kk = *(const float4*)(Kb + (size_t)(kt * AKV + r) * D_ + c4 * 4);
            float4 vv = *(const float4*)(Vb + (size_t)(kt * AKV + r) * D_ + c4 * 4);
            float* kd = sK + r * ASTR + c4 * 4;
            float* vd = sV + r * ASTR + c4 * 4;
            kd[0] = kk.x; kd[1] = kk.y; kd[2] = kk.z; kd[3] = kk.w;
            vd[0] = vv.x; vd[1] = vv.y; vd[2] = vv.z; vd[3] = vv.w;
        }
        __syncthreads();

        // S = Q K^T  (Q pre-scaled)
        float sreg[8][4];
#pragma unroll
        for (int i = 0; i < 8; i++)
#pragma unroll
            for (int j = 0; j < 4; j++) sreg[i][j] = 0.f;

        for (int d = 0; d < DH_; d++) {
            float qv[8], kv[4];
#pragma unroll
            for (int i = 0; i < 8; i++) qv[i] = sQ[(ty * 8 + i) * ASTR + d];
#pragma unroll
            for (int j = 0; j < 4; j++) kv[j] = sK[(tx * 4 + j) * ASTR + d];
#pragma unroll
            for (int i = 0; i < 8; i++)
#pragma unroll
                for (int j = 0; j < 4; j++) sreg[i][j] += qv[i] * kv[j];
        }

        // online softmax update + write P to smem
#pragma unroll
        for (int i = 0; i < 8; i++) {
            float mx = fmaxf(fmaxf(sreg[i][0], sreg[i][1]),
                             fmaxf(sreg[i][2], sreg[i][3]));
#pragma unroll
            for (int o = 8; o > 0; o >>= 1)
                mx = fmaxf(mx, __shfl_xor_sync(0xffffffffu, mx, o));
            float mn = fmaxf(m[i], mx);
            float corr = __expf(m[i] - mn);
            float rs = 0.f;
#pragma unroll
            for (int j = 0; j < 4; j++) {
                float p = __expf(sreg[i][j] - mn);
                sreg[i][j] = p;
                rs += p;
            }
#pragma unroll
            for (int o = 8; o > 0; o >>= 1)
                rs += __shfl_xor_sync(0xffffffffu, rs, o);
            l[i] = l[i] * corr + rs;
            m[i] = mn;
#pragma unroll
            for (int j = 0; j < 4; j++) acc[i][j] *= corr;
#pragma unroll
            for (int j = 0; j < 4; j++)
                sP[(ty * 8 + i) * ASTR + tx * 4 + j] = sreg[i][j];
        }
        __syncthreads();

        // O += P @ V
        for (int k = 0; k < AKV; k++) {
            float pv[8], vv[4];
#pragma unroll
            for (int i = 0; i < 8; i++) pv[i] = sP[(ty * 8 + i) * ASTR + k];
#pragma unroll
            for (int j = 0; j < 4; j++) vv[j] = sV[k * ASTR + tx * 4 + j];
#pragma unroll
            for (int i = 0; i < 8; i++)
#pragma unroll
                for (int j = 0; j < 4; j++) acc[i][j] += pv[i] * vv[j];
        }
    }

#pragma unroll
    for (int i = 0; i < 8; i++) {
        float inv = 1.f / l[i];
        float* op = Og + (size_t)(b * S_ + q0 + ty * 8 + i) * D_ + h * DH_ + tx * 4;
        op[0] = acc[i][0] * inv; op[1] = acc[i][1] * inv;
        op[2] = acc[i][2] * inv; op[3] = acc[i][3] * inv;
    }
}

// ---------------------------------------------------------------------------
// LayerNorm over last dim (1024): one CTA per row, 256 threads x 4 elems
// ---------------------------------------------------------------------------
__global__ void __launch_bounds__(256) ln_kernel(
    const float* __restrict__ X, const float* __restrict__ gw,
    const float* __restrict__ bw, float* __restrict__ Y)
{
    __shared__ float red[8];
    __shared__ float s_mu, s_inv;
    const int row = blockIdx.x, tid = threadIdx.x;
    const float* x = X + (size_t)row * D_;

    float4 xv = *(const float4*)(x + tid * 4);
    float s = xv.x + xv.y + xv.z + xv.w;
#pragma unroll
    for (int o = 16; o > 0; o >>= 1) s += __shfl_xor_sync(0xffffffffu, s, o);
    if ((tid & 31) == 0) red[tid >> 5] = s;
    __syncthreads();
    if (tid == 0) {
        float t = 0.f;
#pragma unroll
        for (int i = 0; i < 8; i++) t += red[i];
        s_mu = t * (1.0f / D_);
    }
    __syncthreads();
    float mu = s_mu;
    float d0 = xv.x - mu, d1 = xv.y - mu, d2 = xv.z - mu, d3 = xv.w - mu;
    float ss = d0 * d0 + d1 * d1 + d2 * d2 + d3 * d3;
#pragma unroll
    for (int o = 16; o > 0; o >>= 1) ss += __shfl_xor_sync(0xffffffffu, ss, o);
    if ((tid & 31) == 0) red[tid >> 5] = ss;
    __syncthreads();
    if (tid == 0) {
        float t = 0.f;
#pragma unroll
        for (int i = 0; i < 8; i++) t += red[i];
        s_inv = rsqrtf(t * (1.0f / D_) + 1e-5f);
    }
    __syncthreads();
    float inv = s_inv;
    float4 gv = *(const float4*)(gw + tid * 4);
    float4 bv = *(const float4*)(bw + tid * 4);
    float4 o;
    o.x = d0 * inv * gv.x + bv.x;
    o.y = d1 * inv * gv.y + bv.y;
    o.z = d2 * inv * gv.z + bv.z;
    o.w = d3 * inv * gv.w + bv.w;
    *(float4*)(Y + (size_t)row * D_ + tid * 4) = o;
}

// ---------------------------------------------------------------------------
// Host orchestration
// ---------------------------------------------------------------------------
extern "C" void kernel_launch(void* const* d_in, const int* in_sizes, int n_in,
                              void* d_out, int out_size)
{
    const float* qm  = (const float*)d_in[0];
    const float* mA  = (const float*)d_in[1];
    const float* mB  = (const float*)d_in[2];
    const float* Wq1 = (const float*)d_in[3];
    const float* bq1 = (const float*)d_in[4];
    const float* Wk1 = (const float*)d_in[5];
    const float* bk1 = (const float*)d_in[6];
    const float* Wv1 = (const float*)d_in[7];
    const float* bv1 = (const float*)d_in[8];
    const float* Wo1 = (const float*)d_in[9];
    const float* bo1 = (const float*)d_in[10];
    const float* Wq2 = (const float*)d_in[11];
    const float* bq2 = (const float*)d_in[12];
    const float* Wk2 = (const float*)d_in[13];
    const float* bk2 = (const float*)d_in[14];
    const float* Wv2 = (const float*)d_in[15];
    const float* bv2 = (const float*)d_in[16];
    const float* Wo2 = (const float*)d_in[17];
    const float* bo2 = (const float*)d_in[18];
    const float* W1  = (const float*)d_in[19];
    const float* b1  = (const float*)d_in[20];
    const float* W2  = (const float*)d_in[21];
    const float* b2  = (const float*)d_in[22];
    const float* g1  = (const float*)d_in[23];
    const float* be1 = (const float*)d_in[24];
    const float* g2  = (const float*)d_in[25];
    const float* be2 = (const float*)d_in[26];
    const float* g3  = (const float*)d_in[27];
    const float* be3 = (const float*)d_in[28];
    float* out = (float*)d_out;

    float *pWq, *pWk, *pWv, *pQ, *pK, *pV, *pAttn, *pX1, *pX2, *pTmp, *pFfh;
    cudaGetSymbolAddress((void**)&pWq,   g_Wq);
    cudaGetSymbolAddress((void**)&pWk,   g_Wk);
    cudaGetSymbolAddress((void**)&pWv,   g_Wv);
    cudaGetSymbolAddress((void**)&pQ,    g_Q);
    cudaGetSymbolAddress((void**)&pK,    g_K);
    cudaGetSymbolAddress((void**)&pV,    g_V);
    cudaGetSymbolAddress((void**)&pAttn, g_attn);
    cudaGetSymbolAddress((void**)&pX1,   g_x1);
    cudaGetSymbolAddress((void**)&pX2,   g_x2);
    cudaGetSymbolAddress((void**)&pTmp,  g_tmp);
    cudaGetSymbolAddress((void**)&pFfh,  g_ffh);

    constexpr int ATTN_SMEM = (AQ + AQ + AKV + AKV) * ASTR * (int)sizeof(float);
    cudaFuncSetAttribute(attn_kernel, cudaFuncAttributeMaxDynamicSharedMemorySize,
                         ATTN_SMEM);

    const dim3 gproj(D_ / 128, M_ / 128);          // 8 x 32
    const dim3 gffn(HID_ / 128, M_ / 128);         // 32 x 32
    const dim3 agrid(S_ / AQ, H_, B_);             // 8 x 16 x 4
    const int rgrid = (D_ * D_) / 256;

    // ---- attention 1 (query = qm, kv = mA) ----
    repack_w_kernel<<<rgrid, 256>>>(Wq1, pWq);
    repack_w_kernel<<<rgrid, 256>>>(Wk1, pWk);
    repack_w_kernel<<<rgrid, 256>>>(Wv1, pWv);
    gemm_kernel<0><<<gproj, 256>>>(qm, pWq, bq1, nullptr, pQ, M_, D_, D_);
    gemm_kernel<0><<<gproj, 256>>>(mA, pWk, bk1, nullptr, pK, M_, D_, D_);
    gemm_kernel<0><<<gproj, 256>>>(mA, pWv, bv1, nullptr, pV, M_, D_, D_);
    attn_kernel<<<agrid, 256, ATTN_SMEM>>>(pQ, pK, pV, pAttn);
    gemm_kernel<1><<<gproj, 256>>>(pAttn, Wo1, bo1, qm, pTmp, M_, D_, D_);
    ln_kernel<<<M_, 256>>>(pTmp, g1, be1, pX1);

    // ---- attention 2 (query = x1, kv = mB) ----
    repack_w_kernel<<<rgrid, 256>>>(Wq2, pWq);
    repack_w_kernel<<<rgrid, 256>>>(Wk2, pWk);
    repack_w_kernel<<<rgrid, 256>>>(Wv2, pWv);
    gemm_kernel<0><<<gproj, 256>>>(pX1, pWq, bq2, nullptr, pQ, M_, D_, D_);
    gemm_kernel<0><<<gproj, 256>>>(mB, pWk, bk2, nullptr, pK, M_, D_, D_);
    gemm_kernel<0><<<gproj, 256>>>(mB, pWv, bv2, nullptr, pV, M_, D_, D_);
    attn_kernel<<<agrid, 256, ATTN_SMEM>>>(pQ, pK, pV, pAttn);
    gemm_kernel<1><<<gproj, 256>>>(pAttn, Wo2, bo2, pX1, pTmp, M_, D_, D_);
    ln_kernel<<<M_, 256>>>(pTmp, g2, be2, pX2);

    // ---- feedforward ----
    gemm_kernel<2><<<gffn, 256>>>(pX2, W1, b1, nullptr, pFfh, M_, HID_, D_);
    gemm_kernel<1><<<gproj, 256>>>(pFfh, W2, b2, pX2, pTmp, M_, D_, HID_);
    ln_kernel<<<M_, 256>>>(pTmp, g3, be3, out);
}

// round 4
// speedup vs baseline: 2.1771x; 2.1771x over previous
#include <cuda_runtime.h>
#include <math.h>
#include <stdint.h>

// Problem constants
#define D_    1024
#define H_    16
#define DH_   64
#define HID_  4096
#define B_    4
#define S_    1024
#define M_    4096   // B_*S_

// ---------------------------------------------------------------------------
// Helpers
// ---------------------------------------------------------------------------
__device__ __forceinline__ uint32_t smem_u32(const void* p) {
    uint32_t a;
    asm("{ .reg .u64 t; cvta.to.shared.u64 t, %1; cvt.u32.u64 %0, t; }"
        : "=r"(a) : "l"(p));
    return a;
}

#define SMEM_SWIZZLE_128B(b) ((b) ^ (((b) >> 3) & 0x70))

__device__ __forceinline__ float to_tf32(float x) {
    uint32_t u;
    asm("cvt.rna.tf32.f32 %0, %1;" : "=r"(u) : "f"(x));
    return __uint_as_float(u);
}

__device__ __forceinline__ void ldsm_x4(uint32_t addr, uint32_t& r0, uint32_t& r1,
                                        uint32_t& r2, uint32_t& r3) {
    asm volatile("ldmatrix.sync.aligned.m8n8.x4.shared.b16 {%0,%1,%2,%3}, [%4];"
                 : "=r"(r0), "=r"(r1), "=r"(r2), "=r"(r3) : "r"(addr));
}

__device__ __forceinline__ void mma_tf32(float* d, const uint32_t* a,
                                         uint32_t b0, uint32_t b1) {
    asm volatile(
        "mma.sync.aligned.m16n8k8.row.col.f32.tf32.tf32.f32 "
        "{%0,%1,%2,%3}, {%4,%5,%6,%7}, {%8,%9}, {%0,%1,%2,%3};"
        : "+f"(d[0]), "+f"(d[1]), "+f"(d[2]), "+f"(d[3])
        : "r"(a[0]), "r"(a[1]), "r"(a[2]), "r"(a[3]), "r"(b0), "r"(b1));
}

// ---------------------------------------------------------------------------
// Scratch (static __device__ arrays; no allocations allowed)
// ---------------------------------------------------------------------------
__device__ float g_Wqt[D_ * D_];
__device__ float g_Wkt[D_ * D_];
__device__ float g_Wvt[D_ * D_];
__device__ float g_Wot[D_ * D_];
__device__ float g_W1t[D_ * HID_];
__device__ float g_W2t[HID_ * D_];
__device__ float g_rA[M_ * D_];
__device__ float g_Q[M_ * D_];
__device__ float g_K[M_ * D_];
__device__ float g_V[M_ * D_];
__device__ float g_attn[M_ * D_];
__device__ float g_x1[M_ * D_];
__device__ float g_x2[M_ * D_];
__device__ float g_tmp[M_ * D_];
__device__ float g_ffh[M_ * HID_];

// ---------------------------------------------------------------------------
// Weight prep: per-head [H, D, DH] -> [H*DH, D] K-major, tf32-rounded
// ---------------------------------------------------------------------------
__global__ void repack_head_t(const float* __restrict__ W, float* __restrict__ Wt)
{
    __shared__ float t[32][33];
    const int h = blockIdx.z;
    const float* Wh = W + (size_t)h * (D_ * DH_);
    const int n0 = blockIdx.x * 32, k0 = blockIdx.y * 32;
    const int tx = threadIdx.x, ty = threadIdx.y;
#pragma unroll
    for (int j = 0; j < 4; j++)
        t[ty + 8 * j][tx] = Wh[(size_t)(k0 + ty + 8 * j) * DH_ + n0 + tx];
    __syncthreads();
#pragma unroll
    for (int j = 0; j < 4; j++)
        Wt[(size_t)(h * DH_ + n0 + ty + 8 * j) * D_ + k0 + tx] =
            to_tf32(t[tx][ty + 8 * j]);
}

// Generic [K, N] -> [N, K] transpose, tf32-rounded. grid (N/32, K/32), block (32,8)
__global__ void transpose_rn(const float* __restrict__ W, float* __restrict__ Wt,
                             int K, int N)
{
    __shared__ float t[32][33];
    const int n0 = blockIdx.x * 32, k0 = blockIdx.y * 32;
    const int tx = threadIdx.x, ty = threadIdx.y;
#pragma unroll
    for (int j = 0; j < 4; j++)
        t[ty + 8 * j][tx] = W[(size_t)(k0 + ty + 8 * j) * N + n0 + tx];
    __syncthreads();
#pragma unroll
    for (int j = 0; j < 4; j++)
        Wt[(size_t)(n0 + ty + 8 * j) * K + k0 + tx] = to_tf32(t[tx][ty + 8 * j]);
}

// Elementwise round-to-tf32 copy (float4 vectorized)
__global__ void rc_kernel(const float* __restrict__ x, float* __restrict__ y)
{
    int i = blockIdx.x * 256 + threadIdx.x;
    float4 v = ((const float4*)x)[i];
    v.x = to_tf32(v.x); v.y = to_tf32(v.y);
    v.z = to_tf32(v.z); v.w = to_tf32(v.w);
    ((float4*)y)[i] = v;
}

// ---------------------------------------------------------------------------
// tf32 mma.sync GEMM: C[M,N] = A[M,K] @ Bt[N,K]^T (+bias [+res] [relu+round])
// MODE 0: +bias   MODE 1: +bias+residual   MODE 2: relu(+bias), tf32-rounded
// CTA tile 128x128, BK=32, 8 warps (warp tile 64x32), 3-stage cp.async ring.
// ---------------------------------------------------------------------------
#define NS 3
#define GBM 128
#define GBN 128
#define GBK 32
#define STAGE_B 32768            // (128*32 + 128*32) * 4 bytes
#define TCG_SMEM (1024 + NS * STAGE_B + 512)

__device__ __forceinline__ void ld_stage(uint32_t sA, uint32_t sB,
    const float* __restrict__ Ag, const float* __restrict__ Bg, int K, int tid)
{
#pragma unroll
    for (int u = 0; u < 4; u++) {
        int ch = u * 256 + tid;          // 0..1023
        int row = ch >> 3;
        int c = ch & 7;
        uint32_t off = SMEM_SWIZZLE_128B((uint32_t)(row * 128 + c * 16));
        const float* srcA = Ag + (size_t)row * K + c * 4;
        const float* srcB = Bg + (size_t)row * K + c * 4;
        asm volatile("cp.async.cg.shared.global [%0], [%1], 16;\n"
                     :: "r"(sA + off), "l"(srcA) : "memory");
        asm volatile("cp.async.cg.shared.global [%0], [%1], 16;\n"
                     :: "r"(sB + off), "l"(srcB) : "memory");
    }
}

template <int MODE>
__global__ void __launch_bounds__(256, 2)
tc_gemm(const float* __restrict__ A, const float* __restrict__ Bt,
        const float* __restrict__ bias, const float* __restrict__ res,
        float* __restrict__ C, int M, int N, int K)
{
    extern __shared__ char smem_raw[];
    const uint32_t sbase = smem_u32(smem_raw);
    const uint32_t stages = (sbase + 1023) & ~1023u;
    float* biasS = (float*)(smem_raw + (stages - sbase) + NS * STAGE_B);

    const int tid = threadIdx.x;
    const int wid = tid >> 5, lane = tid & 31;
    const int wm = wid >> 2;             // 0..1  (64-row slab)
    const int wn = wid & 3;              // 0..3  (32-col slab)
    const int rowBase = blockIdx.y * GBM;
    const int colBase = blockIdx.x * GBN;

    if (tid < 128) biasS[tid] = bias[colBase + tid];

    // per-lane ldmatrix addressing components
    const uint32_t xorv = (uint32_t)(lane & 7) << 4;
    const uint32_t rowAoff = (lane & 7) + ((lane >> 3) & 1) * 8;
    const uint32_t colAadd = (lane >> 4) & 1;
    const uint32_t rowBoff = (lane & 7) + ((lane >> 4) & 1) * 8;
    const uint32_t colBadd = (lane >> 3) & 1;

    const float* Abase = A + (size_t)rowBase * K;
    const float* Bbase = Bt + (size_t)colBase * K;
    const int nCh = K / GBK;

    float acc[4][4][4];
#pragma unroll
    for (int mi = 0; mi < 4; mi++)
#pragma unroll
        for (int ni = 0; ni < 4; ni++)
#pragma unroll
            for (int q = 0; q < 4; q++) acc[mi][ni][q] = 0.f;

    // prologue: stages 0..NS-2
#pragma unroll
    for (int p = 0; p < NS - 1; p++) {
        ld_stage(stages + p * STAGE_B, stages + p * STAGE_B + 16384,
                 Abase + p * GBK, Bbase + p * GBK, K, tid);
        asm volatile("cp.async.commit_group;\n" ::: "memory");
    }

    for (int i = 0; i < nCh; i++) {
        const int j = i + NS - 1;
        if (j < nCh)
            asm volatile("cp.async.wait_group 1;\n" ::: "memory");
        else
            asm volatile("cp.async.wait_group 0;\n" ::: "memory");
        __syncthreads();

        if (j < nCh) {
            const int t = j % NS;
            ld_stage(stages + t * STAGE_B, stages + t * STAGE_B + 16384,
                     Abase + (size_t)j * GBK, Bbase + (size_t)j * GBK, K, tid);
            asm volatile("cp.async.commit_group;\n" ::: "memory");
        }

        const int s = i % NS;
        const uint32_t sA = stages + s * STAGE_B;
        const uint32_t sB = sA + 16384;

#pragma unroll
        for (int ks = 0; ks < 4; ks++) {
            uint32_t a[4][4], bfr[2][4];
#pragma unroll
            for (int mi = 0; mi < 4; mi++) {
                uint32_t row = wm * 64 + mi * 16 + rowAoff;
                uint32_t addr = sA + row * 128 +
                    ((((uint32_t)(ks * 2) + colAadd) << 4) ^ xorv);
                ldsm_x4(addr, a[mi][0], a[mi][1], a[mi][2], a[mi][3]);
            }
#pragma unroll
            for (int nb = 0; nb < 2; nb++) {
                uint32_t row = wn * 32 + nb * 16 + rowBoff;
                uint32_t addr = sB + row * 128 +
                    ((((uint32_t)(ks * 2) + colBadd) << 4) ^ xorv);
                ldsm_x4(addr, bfr[nb][0], bfr[nb][1], bfr[nb][2], bfr[nb][3]);
            }
#pragma unroll
            for (int mi = 0; mi < 4; mi++)
#pragma unroll
                for (int ni = 0; ni < 4; ni++) {
                    uint32_t b0 = bfr[ni >> 1][(ni & 1) * 2 + 0];
                    uint32_t b1 = bfr[ni >> 1][(ni & 1) * 2 + 1];
                    mma_tf32(acc[mi][ni], a[mi], b0, b1);
                }
        }
    }

    // epilogue
#pragma unroll
    for (int mi = 0; mi < 4; mi++) {
        const int r0 = rowBase + wm * 64 + mi * 16 + (lane >> 2);
#pragma unroll
        for (int ni = 0; ni < 4; ni++) {
            const int cl = wn * 32 + ni * 8 + (lane & 3) * 2;
            const int c = colBase + cl;
            const float bx = biasS[cl], by = biasS[cl + 1];
            float v0 = acc[mi][ni][0] + bx;
            float v1 = acc[mi][ni][1] + by;
            float v2 = acc[mi][ni][2] + bx;
            float v3 = acc[mi][ni][3] + by;
            if (MODE == 1) {
                float2 rA = *(const float2*)(res + (size_t)r0 * N + c);
                float2 rB = *(const float2*)(res + (size_t)(r0 + 8) * N + c);
                v0 += rA.x; v1 += rA.y; v2 += rB.x; v3 += rB.y;
            }
            if (MODE == 2) {
                v0 = to_tf32(fmaxf(v0, 0.f));
                v1 = to_tf32(fmaxf(v1, 0.f));
                v2 = to_tf32(fmaxf(v2, 0.f));
                v3 = to_tf32(fmaxf(v3, 0.f));
            }
            *(float2*)(C + (size_t)r0 * N + c) = make_float2(v0, v1);
            *(float2*)(C + (size_t)(r0 + 8) * N + c) = make_float2(v2, v3);
        }
    }
}

// ---------------------------------------------------------------------------
// Fused attention (flash-style, online softmax); output tf32-rounded
// ---------------------------------------------------------------------------
#define AQ   128
#define AKV  64
#define ASTR 65

__global__ void __launch_bounds__(256) attn_kernel(
    const float* __restrict__ Qg, const float* __restrict__ Kg,
    const float* __restrict__ Vg, float* __restrict__ Og)
{
    extern __shared__ float sm[];
    float* sQ = sm;
    float* sP = sQ + AQ * ASTR;
    float* sK = sP + AQ * ASTR;
    float* sV = sK + AKV * ASTR;

    const int b = blockIdx.z, h = blockIdx.y;
    const int q0 = blockIdx.x * AQ;
    const int tid = threadIdx.x;
    const int tx = tid & 15;
    const int ty = tid >> 4;

    const float* Qb = Qg + (size_t)(b * S_ + q0) * D_ + h * DH_;
    const float* Kb = Kg + (size_t)(b * S_) * D_ + h * DH_;
    const float* Vb = Vg + (size_t)(b * S_) * D_ + h * DH_;

#pragma unroll
    for (int u = 0; u < 8; u++) {
        int v = u * 256 + tid;
        int r = v >> 4;
        int c4 = v & 15;
        float4 q = *(const float4*)(Qb + (size_t)r * D_ + c4 * 4);
        float* dst = sQ + r * ASTR + c4 * 4;
        dst[0] = q.x * 0.125f; dst[1] = q.y * 0.125f;
        dst[2] = q.z * 0.125f; dst[3] = q.w * 0.125f;
    }

    float m[8], l[8], acc[8][4];
#pragma unroll
    for (int i = 0; i < 8; i++) {
        m[i] = -1e30f; l[i] = 0.f;
#pragma unroll
        for (int j = 0; j < 4; j++) acc[i][j] = 0.f;
    }

    for (int kt = 0; kt < S_ / AKV; kt++) {
        __syncthreads();
#pragma unroll
        for (int u = 0; u < 4; u++) {
            int v = u * 256 + tid;
            int r = v >> 4;
            int c4 = v & 15;
            float4 kk = *(const float4*)(Kb + (size_t)(kt * AKV + r) * D_ + c4 * 4);
            float4 vv = *(const float4*)(Vb + (size_t)(kt * AKV + r) * D_ + c4 * 4);
            float* kd = sK + r * ASTR + c4 * 4;
            float* vd = sV + r * ASTR + c4 * 4;
            kd[0] = kk.x; kd[1] = kk.y; kd[2] = kk.z; kd[3] = kk.w;
            vd[0] = vv.x; vd[1] = vv.y; vd[2] = vv.z; vd[3] = vv.w;
        }
        __syncthreads();

        float sreg[8][4];
#pragma unroll
        for (int i = 0; i < 8; i++)
#pragma unroll
            for (int j = 0; j < 4; j++) sreg[i][j] = 0.f;

        for (int d = 0; d < DH_; d++) {
            float qv[8], kv[4];
#pragma unroll
            for (int i = 0; i < 8; i++) qv[i] = sQ[(ty * 8 + i) * ASTR + d];
#pragma unroll
            for (int j = 0; j < 4; j++) kv[j] = sK[(tx * 4 + j) * ASTR + d];
#pragma unroll
            for (int i = 0; i < 8; i++)
#pragma unroll
                for (int j = 0; j < 4; j++) sreg[i][j] += qv[i] * kv[j];
        }

#pragma unroll
        for (int i = 0; i < 8; i++) {
            float mx = fmaxf(fmaxf(sreg[i][0], sreg[i][1]),
                             fmaxf(sreg[i][2], sreg[i][3]));
#pragma unroll
            for (int o = 8; o > 0; o >>= 1)
                mx = fmaxf(mx, __shfl_xor_sync(0xffffffffu, mx, o));
            float mn = fmaxf(m[i], mx);
            float corr = __expf(m[i] - mn);
            float rs = 0.f;
#pragma unroll
            for (int j = 0; j < 4; j++) {
                float p = __expf(sreg[i][j] - mn);
                sreg[i][j] = p;
                rs += p;
            }
#pragma unroll
            for (int o = 8; o > 0; o >>= 1)
                rs += __shfl_xor_sync(0xffffffffu, rs, o);
            l[i] = l[i] * corr + rs;
            m[i] = mn;
#pragma unroll
            for (int j = 0; j < 4; j++) acc[i][j] *= corr;
#pragma unroll
            for (int j = 0; j < 4; j++)
                sP[(ty * 8 + i) * ASTR + tx * 4 + j] = sreg[i][j];
        }
        __syncthreads();

        for (int k = 0; k < AKV; k++) {
            float pv[8], vv[4];
#pragma unroll
            for (int i = 0; i < 8; i++) pv[i] = sP[(ty * 8 + i) * ASTR + k];
#pragma unroll
            for (int j = 0; j < 4; j++) vv[j] = sV[k * ASTR + tx * 4 + j];
#pragma unroll
            for (int i = 0; i < 8; i++)
#pragma unroll
                for (int j = 0; j < 4; j++) acc[i][j] += pv[i] * vv[j];
        }
    }

#pragma unroll
    for (int i = 0; i < 8; i++) {
        float inv = 1.f / l[i];
        float* op = Og + (size_t)(b * S_ + q0 + ty * 8 + i) * D_ + h * DH_ + tx * 4;
        op[0] = to_tf32(acc[i][0] * inv);
        op[1] = to_tf32(acc[i][1] * inv);
        op[2] = to_tf32(acc[i][2] * inv);
        op[3] = to_tf32(acc[i][3] * inv);
    }
}

// ---------------------------------------------------------------------------
// LayerNorm over last dim (1024): one CTA per row, 256 threads x 4 elems
// ---------------------------------------------------------------------------
__global__ void __launch_bounds__(256) ln_kernel(
    const float* __restrict__ X, const float* __restrict__ gw,
    const float* __restrict__ bw, float* __restrict__ Y)
{
    __shared__ float red[8];
    __shared__ float s_mu, s_inv;
    const int row = blockIdx.x, tid = threadIdx.x;
    const float* x = X + (size_t)row * D_;

    float4 xv = *(const float4*)(x + tid * 4);
    float s = xv.x + xv.y + xv.z + xv.w;
#pragma unroll
    for (int o = 16; o > 0; o >>= 1) s += __shfl_xor_sync(0xffffffffu, s, o);
    if ((tid & 31) == 0) red[tid >> 5] = s;
    __syncthreads();
    if (tid == 0) {
        float t = 0.f;
#pragma unroll
        for (int i = 0; i < 8; i++) t += red[i];
        s_mu = t * (1.0f / D_);
    }
    __syncthreads();
    float mu = s_mu;
    float d0 = xv.x - mu, d1 = xv.y - mu, d2 = xv.z - mu, d3 = xv.w - mu;
    float ss = d0 * d0 + d1 * d1 + d2 * d2 + d3 * d3;
#pragma unroll
    for (int o = 16; o > 0; o >>= 1) ss += __shfl_xor_sync(0xffffffffu, ss, o);
    if ((tid & 31) == 0) red[tid >> 5] = ss;
    __syncthreads();
    if (tid == 0) {
        float t = 0.f;
#pragma unroll
        for (int i = 0; i < 8; i++) t += red[i];
        s_inv = rsqrtf(t * (1.0f / D_) + 1e-5f);
    }
    __syncthreads();
    float inv = s_inv;
    float4 gv = *(const float4*)(gw + tid * 4);
    float4 bv = *(const float4*)(bw + tid * 4);
    float4 o;
    o.x = d0 * inv * gv.x + bv.x;
    o.y = d1 * inv * gv.y + bv.y;
    o.z = d2 * inv * gv.z + bv.z;
    o.w = d3 * inv * gv.w + bv.w;
    *(float4*)(Y + (size_t)row * D_ + tid * 4) = o;
}

// ---------------------------------------------------------------------------
// Host orchestration
// ---------------------------------------------------------------------------
extern "C" void kernel_launch(void* const* d_in, const int* in_sizes, int n_in,
                              void* d_out, int out_size)
{
    const float* qm  = (const float*)d_in[0];
    const float* mA  = (const float*)d_in[1];
    const float* mB  = (const float*)d_in[2];
    const float* Wq1 = (const float*)d_in[3];
    const float* bq1 = (const float*)d_in[4];
    const float* Wk1 = (const float*)d_in[5];
    const float* bk1 = (const float*)d_in[6];
    const float* Wv1 = (const float*)d_in[7];
    const float* bv1 = (const float*)d_in[8];
    const float* Wo1 = (const float*)d_in[9];
    const float* bo1 = (const float*)d_in[10];
    const float* Wq2 = (const float*)d_in[11];
    const float* bq2 = (const float*)d_in[12];
    const float* Wk2 = (const float*)d_in[13];
    const float* bk2 = (const float*)d_in[14];
    const float* Wv2 = (const float*)d_in[15];
    const float* bv2 = (const float*)d_in[16];
    const float* Wo2 = (const float*)d_in[17];
    const float* bo2 = (const float*)d_in[18];
    const float* W1  = (const float*)d_in[19];
    const float* b1  = (const float*)d_in[20];
    const float* W2  = (const float*)d_in[21];
    const float* b2  = (const float*)d_in[22];
    const float* g1  = (const float*)d_in[23];
    const float* be1 = (const float*)d_in[24];
    const float* g2  = (const float*)d_in[25];
    const float* be2 = (const float*)d_in[26];
    const float* g3  = (const float*)d_in[27];
    const float* be3 = (const float*)d_in[28];
    float* out = (float*)d_out;

    float *pWqt, *pWkt, *pWvt, *pWot, *pW1t, *pW2t, *pRA;
    float *pQ, *pK, *pV, *pAttn, *pX1, *pX2, *pTmp, *pFfh;
    cudaGetSymbolAddress((void**)&pWqt,  g_Wqt);
    cudaGetSymbolAddress((void**)&pWkt,  g_Wkt);
    cudaGetSymbolAddress((void**)&pWvt,  g_Wvt);
    cudaGetSymbolAddress((void**)&pWot,  g_Wot);
    cudaGetSymbolAddress((void**)&pW1t,  g_W1t);
    cudaGetSymbolAddress((void**)&pW2t,  g_W2t);
    cudaGetSymbolAddress((void**)&pRA,   g_rA);
    cudaGetSymbolAddress((void**)&pQ,    g_Q);
    cudaGetSymbolAddress((void**)&pK,    g_K);
    cudaGetSymbolAddress((void**)&pV,    g_V);
    cudaGetSymbolAddress((void**)&pAttn, g_attn);
    cudaGetSymbolAddress((void**)&pX1,   g_x1);
    cudaGetSymbolAddress((void**)&pX2,   g_x2);
    cudaGetSymbolAddress((void**)&pTmp,  g_tmp);
    cudaGetSymbolAddress((void**)&pFfh,  g_ffh);

    constexpr int ATTN_SMEM = (AQ + AQ + AKV + AKV) * ASTR * (int)sizeof(float);
    cudaFuncSetAttribute(attn_kernel, cudaFuncAttributeMaxDynamicSharedMemorySize,
                         ATTN_SMEM);
    cudaFuncSetAttribute(tc_gemm<0>, cudaFuncAttributeMaxDynamicSharedMemorySize,
                         TCG_SMEM);
    cudaFuncSetAttribute(tc_gemm<1>, cudaFuncAttributeMaxDynamicSharedMemorySize,
                         TCG_SMEM);
    cudaFuncSetAttribute(tc_gemm<2>, cudaFuncAttributeMaxDynamicSharedMemorySize,
                         TCG_SMEM);

    const dim3 tblk(32, 8);
    const dim3 ghead(DH_ / 32, D_ / 32, H_);       // per-head repack
    const dim3 gproj(D_ / GBN, M_ / GBM);          // 8 x 32
    const dim3 gffn(HID_ / GBN, M_ / GBM);         // 32 x 32
    const dim3 agrid(S_ / AQ, H_, B_);
    const int rcg = (M_ * D_) / 4 / 256;

    // ---- attention 1 (query = qm, kv = mA) ----
    repack_head_t<<<ghead, tblk>>>(Wq1, pWqt);
    repack_head_t<<<ghead, tblk>>>(Wk1, pWkt);
    repack_head_t<<<ghead, tblk>>>(Wv1, pWvt);
    transpose_rn<<<dim3(D_ / 32, D_ / 32), tblk>>>(Wo1, pWot, D_, D_);
    rc_kernel<<<rcg, 256>>>(qm, pRA);
    tc_gemm<0><<<gproj, 256, TCG_SMEM>>>(pRA, pWqt, bq1, nullptr, pQ, M_, D_, D_);
    rc_kernel<<<rcg, 256>>>(mA, pRA);
    tc_gemm<0><<<gproj, 256, TCG_SMEM>>>(pRA, pWkt, bk1, nullptr, pK, M_, D_, D_);
    tc_gemm<0><<<gproj, 256, TCG_SMEM>>>(pRA, pWvt, bv1, nullptr, pV, M_, D_, D_);
    attn_kernel<<<agrid, 256, ATTN_SMEM>>>(pQ, pK, pV, pAttn);
    tc_gemm<1><<<gproj, 256, TCG_SMEM>>>(pAttn, pWot, bo1, qm, pTmp, M_, D_, D_);
    ln_kernel<<<M_, 256>>>(pTmp, g1, be1, pX1);

    // ---- attention 2 (query = x1, kv = mB) ----
    repack_head_t<<<ghead, tblk>>>(Wq2, pWqt);
    repack_head_t<<<ghead, tblk>>>(Wk2, pWkt);
    repack_head_t<<<ghead, tblk>>>(Wv2, pWvt);
    transpose_rn<<<dim3(D_ / 32, D_ / 32), tblk>>>(Wo2, pWot, D_, D_);
    rc_kernel<<<rcg, 256>>>(pX1, pRA);
    tc_gemm<0><<<gproj, 256, TCG_SMEM>>>(pRA, pWqt, bq2, nullptr, pQ, M_, D_, D_);
    rc_kernel<<<rcg, 256>>>(mB, pRA);
    tc_gemm<0><<<gproj, 256, TCG_SMEM>>>(pRA, pWkt, bk2, nullptr, pK, M_, D_, D_);
    tc_gemm<0><<<gproj, 256, TCG_SMEM>>>(pRA, pWvt, bv2, nullptr, pV, M_, D_, D_);
    attn_kernel<<<agrid, 256, ATTN_SMEM>>>(pQ, pK, pV, pAttn);
    tc_gemm<1><<<gproj, 256, TCG_SMEM>>>(pAttn, pWot, bo2, pX1, pTmp, M_, D_, D_);
    ln_kernel<<<M_, 256>>>(pTmp, g2, be2, pX2);

    // ---- feedforward ----
    transpose_rn<<<dim3(HID_ / 32, D_ / 32), tblk>>>(W1, pW1t, D_, HID_);
    transpose_rn<<<dim3(D_ / 32, HID_ / 32), tblk>>>(W2, pW2t, HID_, D_);
    rc_kernel<<<rcg, 256>>>(pX2, pRA);
    tc_gemm<2><<<gffn, 256, TCG_SMEM>>>(pRA, pW1t, b1, nullptr, pFfh, M_, HID_, D_);
    tc_gemm<1><<<gproj, 256, TCG_SMEM>>>(pFfh, pW2t, b2, pX2, pTmp, M_, D_, HID_);
    ln_kernel<<<M_, 256>>>(pTmp, g3, be3, out);
}